// round 1
// baseline (speedup 1.0000x reference)
#include <cuda_runtime.h>
#include <math.h>

// ---------------------------------------------------------------------------
// Problem: maps[b,y,x] = bilin(out0,64)+bilin(out1,32)+bilin(out2,16) at
// align_corners coords; scores[b] = max over (reflect-pad 5x5 gaussian blur of
// maps). Output layout: d_out[0..255] = scores, d_out[256..] = maps (fp32).
// Fully fused: one kernel writes maps and computes blur+max from a shared
// tile with halo, so the 67MB maps array is written once and never re-read.
// ---------------------------------------------------------------------------

#define TILE  32
#define HALO  2
#define SW    (TILE + 2*HALO)   // 36
#define PITCH (SW + 1)          // 37 (bank-conflict pad)
#define HPITCH (TILE + 1)       // 33

// 1D gaussian weights: exp(-{4,1,0,1,4}/32) normalized (sigma=4, ksize=5)
#define W0 0.18762723f
#define W1 0.20606817f
#define W2 0.21260941f

__device__ unsigned g_score_enc[256];

__device__ __forceinline__ unsigned enc_f(float f) {
    unsigned u = __float_as_uint(f);
    return (u & 0x80000000u) ? ~u : (u | 0x80000000u);
}
__device__ __forceinline__ float dec_f(unsigned u) {
    return (u & 0x80000000u) ? __uint_as_float(u & 0x7fffffffu)
                             : __uint_as_float(~u);
}

// bilinear, align_corners=True, square hxh source, dest 256x256, y/x in [0,255]
__device__ __forceinline__ float bilin(const float* __restrict__ p, int h,
                                       int y, int x) {
    float c  = (float)(h - 1) * (1.0f / 255.0f);
    float ys = (float)y * c;
    float xs = (float)x * c;
    int y0 = (int)ys;            // ys >= 0
    int x0 = (int)xs;
    float fy = ys - (float)y0;
    float fx = xs - (float)x0;
    int y1 = min(y0 + 1, h - 1);
    int x1 = min(x0 + 1, h - 1);
    const float* r0 = p + y0 * h;
    const float* r1 = p + y1 * h;
    float a = r0[x0], b = r0[x1], cc = r1[x0], d = r1[x1];
    float top = fmaf(fx, b - a, a);
    float bot = fmaf(fx, d - cc, cc);
    return fmaf(fy, bot - top, top);
}

__global__ void __launch_bounds__(256, 8)
fused_maps_blur_max(const float* __restrict__ in0,
                    const float* __restrict__ in1,
                    const float* __restrict__ in2,
                    float* __restrict__ maps_out) {
    __shared__ float sm[SW * PITCH];       // maps tile + halo
    __shared__ float hb[SW * HPITCH];      // horizontally blurred

    const int b   = blockIdx.z;
    const int tx0 = blockIdx.x * TILE;
    const int ty0 = blockIdx.y * TILE;
    const int tid = threadIdx.x;

    const float* p0 = in0 + (size_t)b * 64 * 64;
    const float* p1 = in1 + (size_t)b * 32 * 32;
    const float* p2 = in2 + (size_t)b * 16 * 16;

    // 1) compute maps values for the 36x36 halo tile (reflect at image edge)
    #pragma unroll
    for (int i = tid; i < SW * SW; i += 256) {
        int r = i / SW, c = i - r * SW;
        int gy = ty0 - HALO + r;
        int gx = tx0 - HALO + c;
        gy = gy < 0 ? -gy : (gy > 255 ? 510 - gy : gy);
        gx = gx < 0 ? -gx : (gx > 255 ? 510 - gx : gx);
        float v = bilin(p0, 64, gy, gx)
                + bilin(p1, 32, gy, gx)
                + bilin(p2, 16, gy, gx);
        sm[r * PITCH + c] = v;
    }
    __syncthreads();

    // 2) write interior maps (coalesced 128B rows)
    float* mout = maps_out + (size_t)b * 65536;
    #pragma unroll
    for (int i = tid; i < TILE * TILE; i += 256) {
        int r = i >> 5, c = i & 31;
        mout[(ty0 + r) * 256 + tx0 + c] = sm[(r + HALO) * PITCH + (c + HALO)];
    }

    // 3) horizontal 5-tap pass: rows 0..35, cols 0..31 (output-col space)
    #pragma unroll
    for (int i = tid; i < SW * TILE; i += 256) {
        int r = i >> 5, c = i & 31;
        const float* row = &sm[r * PITCH + c];
        float s = W0 * row[0] + W1 * row[1] + W2 * row[2]
                + W1 * row[3] + W0 * row[4];
        hb[r * HPITCH + c] = s;
    }
    __syncthreads();

    // 4) vertical 5-tap pass + local max
    float lmax = -INFINITY;
    #pragma unroll
    for (int i = tid; i < TILE * TILE; i += 256) {
        int r = i >> 5, c = i & 31;
        const float* col = &hb[r * HPITCH + c];
        float s = W0 * col[0]          + W1 * col[HPITCH]
                + W2 * col[2 * HPITCH] + W1 * col[3 * HPITCH]
                + W0 * col[4 * HPITCH];
        lmax = fmaxf(lmax, s);
    }

    // 5) warp max, lane0 atomics into per-batch encoded score
    #pragma unroll
    for (int off = 16; off > 0; off >>= 1)
        lmax = fmaxf(lmax, __shfl_xor_sync(0xFFFFFFFFu, lmax, off));
    if ((tid & 31) == 0)
        atomicMax(&g_score_enc[b], enc_f(lmax));
}

__global__ void init_scores() {
    g_score_enc[threadIdx.x] = 0u;   // < enc of any finite float
}

__global__ void decode_scores(float* __restrict__ out) {
    out[threadIdx.x] = dec_f(g_score_enc[threadIdx.x]);
}

extern "C" void kernel_launch(void* const* d_in, const int* in_sizes, int n_in,
                              void* d_out, int out_size) {
    const float* out0 = (const float*)d_in[0];  // [256,64,64]
    const float* out1 = (const float*)d_in[1];  // [256,32,32]
    const float* out2 = (const float*)d_in[2];  // [256,16,16]
    float* out = (float*)d_out;                 // [256 scores][256*256*256 maps]

    init_scores<<<1, 256>>>();
    dim3 grid(256 / TILE, 256 / TILE, 256);
    fused_maps_blur_max<<<grid, 256>>>(out0, out1, out2, out + 256);
    decode_scores<<<1, 256>>>(out);
}

// round 2
// speedup vs baseline: 1.4388x; 1.4388x over previous
#include <cuda_runtime.h>
#include <math.h>

// ---------------------------------------------------------------------------
// maps[b] = bilin_up(out0,64->256) + bilin_up(out1,32->256) + bilin_up(out2,16->256)
// scores[b] = max( reflect-pad 5x5 gaussian blur of maps[b] )
// d_out = [256 scores][256*256*256 maps]  (fp32)
//
// Strategy: per 32x32 output tile (+2 halo), stage the tiny source-row
// footprint into smem (coalesced), x-upsample once per source row (separable
// bilinear), then y-lerp 3 scales per pixel from packed per-row tables.
// Separable 5-tap blur in smem with float2-vectorized loads. Per-block max
// written to deterministic scratch; tiny second kernel reduces 64->1 per batch.
// ---------------------------------------------------------------------------

#define W0 0.18762723f
#define W1 0.20606817f
#define W2 0.21260941f

#define TILE 32
#define SWID 36           // tile + 2*halo
#define SMP  38           // maps-tile pitch (even for float2)
#define HBP  34           // h-blurred pitch (even)
#define XUP  36           // xup pitch (even)

#define N0 12             // max staged rows, scale 64
#define N1 8              // scale 32
#define N2 6              // scale 16

__device__ float g_partials[256 * 64];

__global__ void __launch_bounds__(256)
fused_maps_blur_max(const float* __restrict__ in0,
                    const float* __restrict__ in1,
                    const float* __restrict__ in2,
                    float* __restrict__ maps_out) {
    __shared__ __align__(16) float s0[N0 * 64];
    __shared__ __align__(16) float s1[N1 * 32];
    __shared__ __align__(16) float s2[N2 * 16];
    __shared__ __align__(16) float xu0[N0 * XUP];
    __shared__ __align__(16) float xu1[N1 * XUP];
    __shared__ __align__(16) float xu2[N2 * XUP];
    __shared__ __align__(16) float4 rowtab[SWID];
    __shared__ int   cx0t[3 * SWID];
    __shared__ float cfxt[3 * SWID];
    __shared__ __align__(16) float sm[SWID * SMP];
    __shared__ __align__(16) float hb[SWID * HBP];
    __shared__ float wmax[8];

    const int tid = threadIdx.x;
    const int b   = blockIdx.z;
    const int tx0 = blockIdx.x * TILE;
    const int ty0 = blockIdx.y * TILE;

    const int gymin = max(0, ty0 - 2);
    const int gymax = min(255, ty0 + 33);

    // staged source-row windows (exact integer math)
    const int rb0 = (gymin * 63) / 255;
    const int rt0 = min((gymax * 63) / 255 + 1, 63);
    const int n0  = rt0 - rb0 + 1;                    // <= 11
    const int rb1 = (gymin * 31) / 255;
    const int rt1 = min((gymax * 31) / 255 + 1, 31);
    const int n1  = rt1 - rb1 + 1;                    // <= 7
    const int rb2 = (gymin * 15) / 255;
    const int rt2 = min((gymax * 15) / 255 + 1, 15);
    const int n2  = rt2 - rb2 + 1;                    // <= 5

    // --- stage source rows (contiguous, coalesced) ---
    {
        const float* p0 = in0 + (size_t)b * 4096 + rb0 * 64;
        for (int i = tid; i < n0 * 64; i += 256) s0[i] = p0[i];
        const float* p1 = in1 + (size_t)b * 1024 + rb1 * 32;
        for (int i = tid; i < n1 * 32; i += 256) s1[i] = p1[i];
        const float* p2 = in2 + (size_t)b * 256 + rb2 * 16;
        for (int i = tid; i < n2 * 16; i += 256) s2[i] = p2[i];
    }

    // --- per-row table: fy for 3 scales + packed local y0/y1 indices ---
    if (tid < SWID) {
        int gy = ty0 - 2 + tid;
        gy = gy < 0 ? -gy : (gy > 255 ? 510 - gy : gy);
        float4 rt;
        int pk;
        {   int num = gy * 63; int y0 = num / 255; int rem = num - 255 * y0;
            int y1 = min(y0 + 1, 63);
            rt.x = (float)rem * (1.0f / 255.0f);
            pk = (y0 - rb0) | ((y1 - rb0) << 4); }
        {   int num = gy * 31; int y0 = num / 255; int rem = num - 255 * y0;
            int y1 = min(y0 + 1, 31);
            rt.y = (float)rem * (1.0f / 255.0f);
            pk |= ((y0 - rb1) << 8) | ((y1 - rb1) << 12); }
        {   int num = gy * 15; int y0 = num / 255; int rem = num - 255 * y0;
            int y1 = min(y0 + 1, 15);
            rt.z = (float)rem * (1.0f / 255.0f);
            pk |= ((y0 - rb2) << 16) | ((y1 - rb2) << 20); }
        rt.w = __int_as_float(pk);
        rowtab[tid] = rt;
    }
    // --- per-col table: x0 (global) + fx for 3 scales ---
    if (tid >= 64 && tid < 64 + 3 * SWID) {
        int idx = tid - 64;
        int s = idx / SWID;
        int c = idx - s * SWID;
        int gx = tx0 - 2 + c;
        gx = gx < 0 ? -gx : (gx > 255 ? 510 - gx : gx);
        int hm1 = (s == 0) ? 63 : ((s == 1) ? 31 : 15);
        int num = gx * hm1;
        int x0 = num / 255;
        int rem = num - 255 * x0;
        cx0t[idx] = x0;
        cfxt[idx] = (float)rem * (1.0f / 255.0f);
    }
    __syncthreads();

    // --- x-upsample each staged row to the 36 tile columns ---
    for (int i = tid; i < n0 * XUP; i += 256) {
        int j = i / XUP, c = i - j * XUP;
        int x0 = cx0t[c];
        int x1 = min(x0 + 1, 63);
        float fx = cfxt[c];
        const float* row = &s0[j * 64];
        float a = row[x0], bb = row[x1];
        xu0[i] = a + fx * (bb - a);
    }
    for (int i = tid; i < n1 * XUP; i += 256) {
        int j = i / XUP, c = i - j * XUP;
        int x0 = cx0t[SWID + c];
        int x1 = min(x0 + 1, 31);
        float fx = cfxt[SWID + c];
        const float* row = &s1[j * 32];
        float a = row[x0], bb = row[x1];
        xu1[i] = a + fx * (bb - a);
    }
    for (int i = tid; i < n2 * XUP; i += 256) {
        int j = i / XUP, c = i - j * XUP;
        int x0 = cx0t[2 * SWID + c];
        int x1 = min(x0 + 1, 15);
        float fx = cfxt[2 * SWID + c];
        const float* row = &s2[j * 16];
        float a = row[x0], bb = row[x1];
        xu2[i] = a + fx * (bb - a);
    }
    __syncthreads();

    // --- y-lerp 3 scales -> 36x36 maps tile (float2 per thread-iter) ---
    for (int i = tid; i < SWID * 18; i += 256) {
        int r = i / 18, c2 = i - r * 18;
        int c = c2 * 2;
        float4 rt = rowtab[r];
        int pk = __float_as_int(rt.w);
        int a0 = pk & 15,          a1 = (pk >> 4) & 15;
        int b0 = (pk >> 8) & 15,   b1 = (pk >> 12) & 15;
        int d0 = (pk >> 16) & 15,  d1 = (pk >> 20) & 15;
        float2 va0 = *(const float2*)&xu0[a0 * XUP + c];
        float2 va1 = *(const float2*)&xu0[a1 * XUP + c];
        float2 vb0 = *(const float2*)&xu1[b0 * XUP + c];
        float2 vb1 = *(const float2*)&xu1[b1 * XUP + c];
        float2 vd0 = *(const float2*)&xu2[d0 * XUP + c];
        float2 vd1 = *(const float2*)&xu2[d1 * XUP + c];
        float vx = (va0.x + rt.x * (va1.x - va0.x))
                 + (vb0.x + rt.y * (vb1.x - vb0.x))
                 + (vd0.x + rt.z * (vd1.x - vd0.x));
        float vy = (va0.y + rt.x * (va1.y - va0.y))
                 + (vb0.y + rt.y * (vb1.y - vb0.y))
                 + (vd0.y + rt.z * (vd1.y - vd0.y));
        *(float2*)&sm[r * SMP + c] = make_float2(vx, vy);
    }
    __syncthreads();

    // --- write interior maps (float2, coalesced) ---
    float* mout = maps_out + (size_t)b * 65536 + (size_t)ty0 * 256 + tx0;
    for (int i = tid; i < TILE * 16; i += 256) {
        int r = i >> 4, j = i & 15;
        int c = 2 * j;
        float2 v = *(const float2*)&sm[(r + 2) * SMP + (c + 2)];
        *(float2*)&mout[r * 256 + c] = v;
    }

    // --- horizontal 5-tap blur: 36 rows x 32 cols ---
    for (int i = tid; i < SWID * 16; i += 256) {
        int r = i >> 4, j = i & 15;
        int c = 2 * j;
        const float* row = &sm[r * SMP + c];
        float2 v01 = *(const float2*)&row[0];
        float2 v23 = *(const float2*)&row[2];
        float2 v45 = *(const float2*)&row[4];
        float o0 = W0 * v01.x + W1 * v01.y + W2 * v23.x + W1 * v23.y + W0 * v45.x;
        float o1 = W0 * v01.y + W1 * v23.x + W2 * v23.y + W1 * v45.x + W0 * v45.y;
        *(float2*)&hb[r * HBP + c] = make_float2(o0, o1);
    }
    __syncthreads();

    // --- vertical 5-tap blur + local max ---
    float lmax = -INFINITY;
    for (int i = tid; i < TILE * 16; i += 256) {
        int r = i >> 4, j = i & 15;
        int c = 2 * j;
        const float* col = &hb[r * HBP + c];
        float2 h0 = *(const float2*)&col[0];
        float2 h1 = *(const float2*)&col[HBP];
        float2 h2 = *(const float2*)&col[2 * HBP];
        float2 h3 = *(const float2*)&col[3 * HBP];
        float2 h4 = *(const float2*)&col[4 * HBP];
        float o0 = W0 * h0.x + W1 * h1.x + W2 * h2.x + W1 * h3.x + W0 * h4.x;
        float o1 = W0 * h0.y + W1 * h1.y + W2 * h2.y + W1 * h3.y + W0 * h4.y;
        lmax = fmaxf(lmax, fmaxf(o0, o1));
    }
    #pragma unroll
    for (int off = 16; off; off >>= 1)
        lmax = fmaxf(lmax, __shfl_xor_sync(0xFFFFFFFFu, lmax, off));
    if ((tid & 31) == 0) wmax[tid >> 5] = lmax;
    __syncthreads();
    if (tid == 0) {
        float m = wmax[0];
        #pragma unroll
        for (int w = 1; w < 8; w++) m = fmaxf(m, wmax[w]);
        g_partials[b * 64 + blockIdx.y * 8 + blockIdx.x] = m;
    }
}

__global__ void reduce_scores(float* __restrict__ out) {
    int b = blockIdx.x;
    int t = threadIdx.x;   // 64 threads
    float v = g_partials[b * 64 + t];
    #pragma unroll
    for (int off = 16; off; off >>= 1)
        v = fmaxf(v, __shfl_xor_sync(0xFFFFFFFFu, v, off));
    __shared__ float s[2];
    if ((t & 31) == 0) s[t >> 5] = v;
    __syncthreads();
    if (t == 0) out[b] = fmaxf(s[0], s[1]);
}

extern "C" void kernel_launch(void* const* d_in, const int* in_sizes, int n_in,
                              void* d_out, int out_size) {
    const float* out0 = (const float*)d_in[0];  // [256,64,64]
    const float* out1 = (const float*)d_in[1];  // [256,32,32]
    const float* out2 = (const float*)d_in[2];  // [256,16,16]
    float* out = (float*)d_out;

    dim3 grid(256 / TILE, 256 / TILE, 256);
    fused_maps_blur_max<<<grid, 256>>>(out0, out1, out2, out + 256);
    reduce_scores<<<256, 64>>>(out);
}

// round 3
// speedup vs baseline: 2.7271x; 1.8954x over previous
#include <cuda_runtime.h>
#include <math.h>

// ---------------------------------------------------------------------------
// maps[b] = bilin_up(out0,64)+bilin_up(out1,32)+bilin_up(out2,16) -> 256x256
// scores[b] = max( reflect-pad 5x5 gaussian blur of maps[b] )
// d_out = [256 scores][256*256*256 maps] fp32.
//
// Grid: 1024 blocks = (batch, quarter-strip of 64 rows), 128 threads = column
// pairs. Incremental register bilinear caches (uniform bracket advances, no
// per-row division, no gathers in steady state), packed f32x2 math, smem ring
// only for the horizontal blur halo, register ring for the vertical blur.
// ---------------------------------------------------------------------------

typedef unsigned long long ull;

#define W0 0.18762723f
#define W1 0.20606817f
#define W2 0.21260941f

__device__ __forceinline__ ull pk2(float a, float b) {
    ull r; asm("mov.b64 %0, {%1,%2};" : "=l"(r) : "f"(a), "f"(b)); return r;
}
__device__ __forceinline__ float2 up2(ull v) {
    float2 r; asm("mov.b64 {%0,%1}, %2;" : "=f"(r.x), "=f"(r.y) : "l"(v)); return r;
}
__device__ __forceinline__ ull f2add(ull a, ull b) {
    ull r; asm("add.rn.f32x2 %0,%1,%2;" : "=l"(r) : "l"(a), "l"(b)); return r;
}
__device__ __forceinline__ ull f2mul(ull a, ull b) {
    ull r; asm("mul.rn.f32x2 %0,%1,%2;" : "=l"(r) : "l"(a), "l"(b)); return r;
}
__device__ __forceinline__ ull f2fma(ull a, ull b, ull c) {
    ull r; asm("fma.rn.f32x2 %0,%1,%2,%3;" : "=l"(r) : "l"(a), "l"(b), "l"(c)); return r;
}

__device__ __align__(16) float g_partials[1024];

// per-scale incremental bilinear cache (thread handles columns c0, c1)
template<int H>
struct SC {
    int x0a, x1a, x0b, x1b;
    float fxa, fxb;
    int rlo;         // first staged source row
    int y0, rem;     // y bracket state: num = y*(H-1) = 255*y0 + rem
    float xha, xhb;  // x-lerped values at source row y0+1 (scalars)
    ull xlo2, xdf2;  // packed x-lerp at y0, packed (hi - lo)
};

template<int H>
__device__ __forceinline__ void col_init(SC<H>& c, int c0, int c1, int rlo) {
    int n0 = c0 * (H - 1);
    c.x0a = n0 / 255;
    c.fxa = (float)(n0 - 255 * c.x0a) * (1.0f / 255.0f);
    c.x1a = min(c.x0a + 1, H - 1);
    int n1 = c1 * (H - 1);
    c.x0b = n1 / 255;
    c.fxb = (float)(n1 - 255 * c.x0b) * (1.0f / 255.0f);
    c.x1b = min(c.x0b + 1, H - 1);
    c.rlo = rlo;
}

template<int H>
__device__ __forceinline__ float xl_a(const SC<H>& c, const float* row) {
    float a = row[c.x0a], b = row[c.x1a];
    return fmaf(c.fxa, b - a, a);
}
template<int H>
__device__ __forceinline__ float xl_b(const SC<H>& c, const float* row) {
    float a = row[c.x0b], b = row[c.x1b];
    return fmaf(c.fxb, b - a, a);
}

template<int H>
__device__ __forceinline__ void sc_init(SC<H>& c, const float* sm, int y) {
    int num = y * (H - 1);
    c.y0  = num / 255;
    c.rem = num - 255 * c.y0;
    const float* rlo = sm + (c.y0 - c.rlo) * H;
    const float* rhi = sm + (min(c.y0 + 1, H - 1) - c.rlo) * H;
    float la = xl_a(c, rlo), lb = xl_b(c, rlo);
    c.xha = xl_a(c, rhi);
    c.xhb = xl_b(c, rhi);
    c.xlo2 = pk2(la, lb);
    c.xdf2 = pk2(c.xha - la, c.xhb - lb);
}

template<int H>
__device__ __forceinline__ ull sc_m(const SC<H>& c) {
    float fy = (float)c.rem * (1.0f / 255.0f);
    return f2fma(pk2(fy, fy), c.xdf2, c.xlo2);
}

template<int H>
__device__ __forceinline__ void sc_adv(SC<H>& c, const float* sm) {
    c.rem += (H - 1);
    if (c.rem >= 255) {          // uniform branch (depends only on row)
        c.rem -= 255;
        c.y0++;
        c.xlo2 = f2add(c.xlo2, c.xdf2);       // new lo = old hi
        const float* rhi = sm + (min(c.y0 + 1, H - 1) - c.rlo) * H;
        float nha = xl_a(c, rhi), nhb = xl_b(c, rhi);
        c.xdf2 = pk2(nha - c.xha, nhb - c.xhb);
        c.xha = nha; c.xhb = nhb;
    }
}

__device__ __forceinline__ void store_mrow(float (*mbuf)[264], int r, float2 mv, int tid) {
    *(float2*)&mbuf[r][2 + 2 * tid] = mv;
    if (tid == 1)        mbuf[r][0]   = mv.x;   // col -2 = reflect col 2
    else if (tid == 0)   mbuf[r][1]   = mv.y;   // col -1 = reflect col 1
    else if (tid == 127) mbuf[r][258] = mv.x;   // col 256 = reflect col 254
    else if (tid == 126) mbuf[r][259] = mv.y;   // col 257 = reflect col 253
}

__device__ __forceinline__ ull hblur_row(const float* mrow, int tid, ull w0p, ull w1p, ull w2p) {
    float2 v01 = *(const float2*)&mrow[2 * tid];
    float2 v23 = *(const float2*)&mrow[2 * tid + 2];
    float2 v45 = *(const float2*)&mrow[2 * tid + 4];
    ull p0 = pk2(v01.x, v01.y);
    ull p1 = pk2(v01.y, v23.x);
    ull p2 = pk2(v23.x, v23.y);
    ull p3 = pk2(v23.y, v45.x);
    ull p4 = pk2(v45.x, v45.y);
    return f2fma(w0p, f2add(p0, p4), f2fma(w1p, f2add(p1, p3), f2mul(w2p, p2)));
}

__global__ void __launch_bounds__(128)
fused_quarter(const float* __restrict__ in0,
              const float* __restrict__ in1,
              const float* __restrict__ in2,
              float* __restrict__ maps) {
    __shared__ __align__(16) float s0[20 * 64];
    __shared__ __align__(16) float s1[12 * 32];
    __shared__ __align__(16) float s2[8 * 16];
    __shared__ __align__(16) float mbuf[8][264];
    __shared__ float wred[4];

    const int tid = threadIdx.x;
    const int bx  = blockIdx.x;
    const int b   = bx >> 2;
    const int q   = bx & 3;
    const int yq0 = q * 64;

    // actual source-row window needed by this strip (incl. blur halo)
    const int amin = max(0, yq0 - 2);
    const int amax = min(255, yq0 + 65);
    const int rlo0 = (amin * 63) / 255, rhi0 = min((amax * 63) / 255 + 1, 63);
    const int rlo1 = (amin * 31) / 255, rhi1 = min((amax * 31) / 255 + 1, 31);
    const int rlo2 = (amin * 15) / 255, rhi2 = min((amax * 15) / 255 + 1, 15);

    // stage sources (coalesced float4)
    {
        const float4* g = (const float4*)(in0 + (size_t)b * 4096 + rlo0 * 64);
        int n = (rhi0 - rlo0 + 1) * 16;
        for (int i = tid; i < n; i += 128) ((float4*)s0)[i] = g[i];
    }
    {
        const float4* g = (const float4*)(in1 + (size_t)b * 1024 + rlo1 * 32);
        int n = (rhi1 - rlo1 + 1) * 8;
        for (int i = tid; i < n; i += 128) ((float4*)s1)[i] = g[i];
    }
    {
        const float4* g = (const float4*)(in2 + (size_t)b * 256 + rlo2 * 16);
        int n = (rhi2 - rlo2 + 1) * 4;
        for (int i = tid; i < n; i += 128) ((float4*)s2)[i] = g[i];
    }

    SC<64> cA; SC<32> cB; SC<16> cC;
    col_init(cA, 2 * tid, 2 * tid + 1, rlo0);
    col_init(cB, 2 * tid, 2 * tid + 1, rlo1);
    col_init(cC, 2 * tid, 2 * tid + 1, rlo2);

    const ull w0p = pk2(W0, W0), w1p = pk2(W1, W1), w2p = pk2(W2, W2);

    __syncthreads();

    // ---- prime: h(yq0-2), h(yq0-1)  (reflect at top edge) ----
    {
        int p0 = (q == 0) ? 2 : yq0 - 2;
        int p1 = (q == 0) ? 1 : yq0 - 1;
        sc_init(cA, s0, p0); sc_init(cB, s1, p0); sc_init(cC, s2, p0);
        store_mrow(mbuf, 0, up2(f2add(f2add(sc_m(cA), sc_m(cB)), sc_m(cC))), tid);
        sc_init(cA, s0, p1); sc_init(cB, s1, p1); sc_init(cC, s2, p1);
        store_mrow(mbuf, 1, up2(f2add(f2add(sc_m(cA), sc_m(cB)), sc_m(cC))), tid);
    }
    __syncthreads();
    ull ha = 0, hb = 0;
    ull hc = hblur_row(&mbuf[0][0], tid, w0p, w1p, w2p);   // h(yq0-2)
    ull hd = hblur_row(&mbuf[1][0], tid, w0p, w1p, w2p);   // h(yq0-1)
    __syncthreads();

    // ---- main strip ----
    sc_init(cA, s0, yq0); sc_init(cB, s1, yq0); sc_init(cC, s2, yq0);

    float* mout = maps + (size_t)b * 65536;
    float lmax = -INFINITY;
    const int nrows = (q < 3) ? 66 : 64;   // q<3 needs 2 extra h rows below
    int done = 0;

    while (done < nrows) {
        int cnt = min(8, nrows - done);
        // phase A: compute m rows, store maps + smem ring
        #pragma unroll
        for (int r = 0; r < 8; ++r) {
            if (r < cnt) {
                int y = yq0 + done + r;
                float2 mv = up2(f2add(f2add(sc_m(cA), sc_m(cB)), sc_m(cC)));
                store_mrow(mbuf, r, mv, tid);
                if (y < yq0 + 64)
                    *(float2*)&mout[y * 256 + 2 * tid] = mv;
                sc_adv(cA, s0); sc_adv(cB, s1); sc_adv(cC, s2);
            }
        }
        __syncthreads();
        // phase B: h-blur + register-ring v-blur + max
        #pragma unroll
        for (int r = 0; r < 8; ++r) {
            if (r < cnt) {
                int y = yq0 + done + r;
                ull he = hblur_row(&mbuf[r][0], tid, w0p, w1p, w2p);
                if (y >= yq0 + 2) {
                    ull vv = f2fma(w0p, f2add(ha, he),
                             f2fma(w1p, f2add(hb, hd), f2mul(w2p, hc)));
                    float2 vf = up2(vv);
                    lmax = fmaxf(lmax, fmaxf(vf.x, vf.y));
                }
                ha = hb; hb = hc; hc = hd; hd = he;
            }
        }
        __syncthreads();
        done += cnt;
    }

    if (q == 3) {
        // ring: ha=h252 hb=h253 hc=h254 hd=h255; reflect rows 256->254, 257->253
        ull v254 = f2fma(w0p, f2add(ha, hc), f2fma(w1p, f2add(hb, hd), f2mul(w2p, hc)));
        ull v255 = f2fma(w0p, f2add(hb, hb), f2fma(w1p, f2add(hc, hc), f2mul(w2p, hd)));
        float2 a4 = up2(v254), a5 = up2(v255);
        lmax = fmaxf(lmax, fmaxf(fmaxf(a4.x, a4.y), fmaxf(a5.x, a5.y)));
    }

    // block max -> partials
    #pragma unroll
    for (int off = 16; off; off >>= 1)
        lmax = fmaxf(lmax, __shfl_xor_sync(0xFFFFFFFFu, lmax, off));
    if ((tid & 31) == 0) wred[tid >> 5] = lmax;
    __syncthreads();
    if (tid == 0)
        g_partials[bx] = fmaxf(fmaxf(wred[0], wred[1]), fmaxf(wred[2], wred[3]));
}

__global__ void reduce4(float* __restrict__ out) {
    int t = threadIdx.x;
    float4 p = ((const float4*)g_partials)[t];
    out[t] = fmaxf(fmaxf(p.x, p.y), fmaxf(p.z, p.w));
}

extern "C" void kernel_launch(void* const* d_in, const int* in_sizes, int n_in,
                              void* d_out, int out_size) {
    const float* out0 = (const float*)d_in[0];  // [256,64,64]
    const float* out1 = (const float*)d_in[1];  // [256,32,32]
    const float* out2 = (const float*)d_in[2];  // [256,16,16]
    float* out = (float*)d_out;

    fused_quarter<<<1024, 128>>>(out0, out1, out2, out + 256);
    reduce4<<<1, 256>>>(out);
}